// round 2
// baseline (speedup 1.0000x reference)
#include <cuda_runtime.h>
#include <cuda_bf16.h>
#include <cstdint>

// Problem dims (fixed)
#define BB 64
#define SS 512
#define II 256
#define HH 512
#define CC 10

// ---------------- scratch (no runtime allocation allowed) ----------------
__device__ float g_pre0[(size_t)BB * SS * HH];   // 64 MB: pre-activations L0; reused as hist1
__device__ float g_hist0[(size_t)BB * SS * HH];  // 64 MB: tanh outputs L0 (input to L1 GEMM)
__device__ float g_pre1[(size_t)BB * SS * HH];   // 64 MB: pre-activations L1
__device__ int   g_flags[2 * 8 * SS];            // per (layer, batch-group, t) completion counters

// ---------------- GEMM: out[m][n] = sum_k A[m][k]*W[n][k] + b1[n] + b2[n] --------
// M = 32768 (B*S), N = 512 (H), K = 256 or 512. Tile 128x64, BK=16, 256 threads, 8x4 microtile.
#define LDA_S 132
#define LDB_S 68

__global__ void gemm_bias_kernel(const float* __restrict__ A,
                                 const float* __restrict__ W,
                                 const float* __restrict__ b1,
                                 const float* __restrict__ b2,
                                 float* __restrict__ out,
                                 int K)
{
    __shared__ float As[16 * LDA_S];
    __shared__ float Bs[16 * LDB_S];

    const int m0 = blockIdx.x * 128;
    const int n0 = blockIdx.y * 64;
    const int tid = threadIdx.x;
    const int tm = tid >> 4;   // 0..15  -> rows tm*8 .. tm*8+7
    const int tn = tid & 15;   // 0..15  -> cols tn*4 .. tn*4+3

    float acc[8][4];
#pragma unroll
    for (int i = 0; i < 8; i++)
#pragma unroll
        for (int j = 0; j < 4; j++) acc[i][j] = 0.f;

    for (int k0 = 0; k0 < K; k0 += 16) {
        // Stage A tile (128 x 16), transposed into As[k][m]
#pragma unroll
        for (int i = 0; i < 2; i++) {
            int f = tid + i * 256;         // 512 float4s
            int r = f >> 2;                // 0..127
            int kq = f & 3;                // 0..3
            float4 v = *(const float4*)(A + (size_t)(m0 + r) * K + k0 + kq * 4);
            As[(kq * 4 + 0) * LDA_S + r] = v.x;
            As[(kq * 4 + 1) * LDA_S + r] = v.y;
            As[(kq * 4 + 2) * LDA_S + r] = v.z;
            As[(kq * 4 + 3) * LDA_S + r] = v.w;
        }
        // Stage B tile (64 x 16), transposed into Bs[k][n]
        {
            int n = tid >> 2;              // 0..63
            int kq = tid & 3;              // 0..3
            float4 v = *(const float4*)(W + (size_t)(n0 + n) * K + k0 + kq * 4);
            Bs[(kq * 4 + 0) * LDB_S + n] = v.x;
            Bs[(kq * 4 + 1) * LDB_S + n] = v.y;
            Bs[(kq * 4 + 2) * LDB_S + n] = v.z;
            Bs[(kq * 4 + 3) * LDB_S + n] = v.w;
        }
        __syncthreads();

#pragma unroll
        for (int kk = 0; kk < 16; kk++) {
            float4 a0 = *(const float4*)&As[kk * LDA_S + tm * 8];
            float4 a1 = *(const float4*)&As[kk * LDA_S + tm * 8 + 4];
            float4 bv = *(const float4*)&Bs[kk * LDB_S + tn * 4];
            float am[8] = {a0.x, a0.y, a0.z, a0.w, a1.x, a1.y, a1.z, a1.w};
            float bn[4] = {bv.x, bv.y, bv.z, bv.w};
#pragma unroll
            for (int i = 0; i < 8; i++)
#pragma unroll
                for (int j = 0; j < 4; j++) acc[i][j] += am[i] * bn[j];
        }
        __syncthreads();
    }

    const int n = n0 + tn * 4;
    float bias[4];
#pragma unroll
    for (int j = 0; j < 4; j++) bias[j] = b1[n + j] + b2[n + j];

#pragma unroll
    for (int i = 0; i < 8; i++) {
        int row = m0 + tm * 8 + i;
        float4 o;
        o.x = acc[i][0] + bias[0];
        o.y = acc[i][1] + bias[1];
        o.z = acc[i][2] + bias[2];
        o.w = acc[i][3] + bias[3];
        *(float4*)(out + (size_t)row * HH + n) = o;
    }
}

// ---------------- Recurrence: h_t = tanh(pre_t + h_{t-1} @ W_hh^T) ----------------
// Grid: 128 CTAs = 8 batch-groups (8 batches each) x 16 j-slices (32 hidden each).
// W slice (32x512) resident in SMEM for all 512 steps. Per step: stage h_{t-1}
// (8x512) from global, K split 8-ways over warps, SMEM reduce, tanh, store history,
// signal per-(bg,t) flag. Readers of step t wait for flag[bg][t-1] == 16.
#define WPAD 516   // 512 + 4 pad: conflict-free float4 LDS across 32 j-lanes

#define RSMEM_FLOATS (32 * WPAD + 8 * 512 + 8 * 8 * 32)
#define RSMEM_BYTES  (RSMEM_FLOATS * 4)

__global__ void rnn_recur_kernel(const float* __restrict__ pre,
                                 const float* __restrict__ whh,
                                 float* __restrict__ hist,
                                 int* __restrict__ flags)
{
    extern __shared__ float sm[];
    float* ws  = sm;                       // [32][WPAD]
    float* hs  = ws + 32 * WPAD;           // [8][512]
    float* red = hs + 8 * 512;             // [8 ks][8 b][32 j]

    const int tid = threadIdx.x;
    const int bg  = blockIdx.x & 7;        // batch group (8 batches)
    const int jg  = blockIdx.x >> 3;       // hidden slice (32 outputs)
    const int jl  = tid & 31;              // j lane
    const int ks  = tid >> 5;              // k partition (64 k each)
    const int b0  = bg * 8;

    // Load this CTA's W_hh slice once (32 rows x 512) into padded SMEM.
#pragma unroll
    for (int i = 0; i < 16; i++) {
        int f = tid + i * 256;             // 4096 float4s
        int j = f >> 7;                    // 0..31
        int k4 = f & 127;                  // 0..127
        float4 v = *(const float4*)(whh + (size_t)(jg * 32 + j) * HH + k4 * 4);
        *(float4*)(ws + j * WPAD + k4 * 4) = v;
    }
    __syncthreads();

    for (int t = 0; t < SS; t++) {
        if (t > 0) {
            if (tid == 0) {
                volatile int* f = (volatile int*)(flags + bg * SS + (t - 1));
                while (*f < 16) { }
                __threadfence();
            }
            __syncthreads();
            // Stage h_{t-1} for our 8 batches (8 x 512 floats)
#pragma unroll
            for (int i = 0; i < 4; i++) {
                int f4 = tid + i * 256;    // 1024 float4s
                int b = f4 >> 7;
                int k4 = f4 & 127;
                float4 v = *(const float4*)(hist + ((size_t)(b0 + b) * SS + (t - 1)) * HH + k4 * 4);
                *(float4*)(hs + b * 512 + k4 * 4) = v;
            }
        } else {
#pragma unroll
            for (int i = 0; i < 4; i++) {
                int f4 = tid + i * 256;
                int b = f4 >> 7;
                int k4 = f4 & 127;
                *(float4*)(hs + b * 512 + k4 * 4) = make_float4(0.f, 0.f, 0.f, 0.f);
            }
        }
        __syncthreads();

        // Partial dot products over our 64-wide K slice, all 8 batches.
        float acc[8];
#pragma unroll
        for (int b = 0; b < 8; b++) acc[b] = 0.f;
        const int kbase = ks * 64;
#pragma unroll
        for (int i = 0; i < 16; i++) {
            int k = kbase + i * 4;
            float4 w4 = *(const float4*)(ws + jl * WPAD + k);
#pragma unroll
            for (int b = 0; b < 8; b++) {
                float4 h4 = *(const float4*)(hs + b * 512 + k);
                acc[b] += w4.x * h4.x + w4.y * h4.y + w4.z * h4.z + w4.w * h4.w;
            }
        }
#pragma unroll
        for (int b = 0; b < 8; b++) red[(ks * 8 + b) * 32 + jl] = acc[b];
        __syncthreads();

        // Reduce across the 8 K-partitions; one output per thread (8b x 32j).
        {
            const int ob = ks;             // 0..7
            const int oj = jl;             // 0..31
            float s = 0.f;
#pragma unroll
            for (int r = 0; r < 8; r++) s += red[(r * 8 + ob) * 32 + oj];
            float p = pre[((size_t)(b0 + ob) * SS + t) * HH + jg * 32 + oj];
            float h = tanhf(p + s);
            hist[((size_t)(b0 + ob) * SS + t) * HH + jg * 32 + oj] = h;
        }
        __threadfence();                   // make our stores L2-visible before signaling
        __syncthreads();
        if (tid == 0) atomicAdd(flags + bg * SS + t, 1);
    }
}

// ---------------- FC head: out[b][c] = h_last[b] . w_fc[c] + b_fc[c] ----------------
__global__ void fc_kernel(const float* __restrict__ hist1,
                          const float* __restrict__ wfc,
                          const float* __restrict__ bfc,
                          float* __restrict__ out)
{
    const int b = blockIdx.x;
    const int c = threadIdx.x >> 5;        // 0..9
    const int lane = threadIdx.x & 31;
    const float* h = hist1 + ((size_t)b * SS + (SS - 1)) * HH;
    float acc = 0.f;
    for (int j = lane; j < HH; j += 32) acc += h[j] * wfc[c * HH + j];
#pragma unroll
    for (int o = 16; o; o >>= 1) acc += __shfl_down_sync(0xffffffffu, acc, o);
    if (lane == 0) out[b * CC + c] = acc + bfc[c];
}

// ---------------- launch ----------------
extern "C" void kernel_launch(void* const* d_in, const int* in_sizes, int n_in,
                              void* d_out, int out_size)
{
    const float* x     = (const float*)d_in[0];
    const float* w_ih0 = (const float*)d_in[1];
    const float* w_hh0 = (const float*)d_in[2];
    const float* b_ih0 = (const float*)d_in[3];
    const float* b_hh0 = (const float*)d_in[4];
    const float* w_ih1 = (const float*)d_in[5];
    const float* w_hh1 = (const float*)d_in[6];
    const float* b_ih1 = (const float*)d_in[7];
    const float* b_hh1 = (const float*)d_in[8];
    const float* w_fc  = (const float*)d_in[9];
    const float* b_fc  = (const float*)d_in[10];
    float* out = (float*)d_out;

    float *pre0, *hist0, *pre1;
    int* flags;
    cudaGetSymbolAddress((void**)&pre0,  g_pre0);
    cudaGetSymbolAddress((void**)&hist0, g_hist0);
    cudaGetSymbolAddress((void**)&pre1,  g_pre1);
    cudaGetSymbolAddress((void**)&flags, g_flags);

    cudaFuncSetAttribute(rnn_recur_kernel,
                         cudaFuncAttributeMaxDynamicSharedMemorySize, RSMEM_BYTES);

    // Reset producer/consumer flags for this replay (graph-capturable).
    cudaMemsetAsync(flags, 0, 2 * 8 * SS * sizeof(int));

    dim3 gemm_grid(BB * SS / 128, HH / 64);

    // Layer 0
    gemm_bias_kernel<<<gemm_grid, 256>>>(x, w_ih0, b_ih0, b_hh0, pre0, II);
    rnn_recur_kernel<<<128, 256, RSMEM_BYTES>>>(pre0, w_hh0, hist0, flags);

    // Layer 1 (hist1 reuses the pre0 buffer)
    gemm_bias_kernel<<<gemm_grid, 256>>>(hist0, w_ih1, b_ih1, b_hh1, pre1, HH);
    rnn_recur_kernel<<<128, 256, RSMEM_BYTES>>>(pre1, w_hh1, pre0, flags + 8 * SS);

    // Head
    fc_kernel<<<BB, CC * 32>>>(pre0, w_fc, b_fc, out);
}

// round 3
// speedup vs baseline: 1.2845x; 1.2845x over previous
#include <cuda_runtime.h>
#include <cstdint>

#define BB 64
#define SS 512
#define II 256
#define HH 512
#define CC 10

// ---------------- scratch ----------------
__device__ float g_pre0[(size_t)BB * SS * HH];   // pre-activations L0; reused as hist1
__device__ float g_hist0[(size_t)BB * SS * HH];  // tanh outputs L0 (input to L1 GEMM)
__device__ float g_pre1[(size_t)BB * SS * HH];   // pre-activations L1
__device__ int   g_flags[2 * 4 * SS];            // per (layer, batch-group, t) counters

// ---------------- helpers ----------------
__device__ __forceinline__ uint32_t f2tf(float x) {
    uint32_t r; asm("cvt.rna.tf32.f32 %0, %1;" : "=r"(r) : "f"(x)); return r;
}
__device__ __forceinline__ void mma8(float* d, const uint32_t* a, const uint32_t* b) {
    asm volatile("mma.sync.aligned.m16n8k8.row.col.f32.tf32.tf32.f32 "
                 "{%0,%1,%2,%3},{%4,%5,%6,%7},{%8,%9},{%0,%1,%2,%3};"
                 : "+f"(d[0]), "+f"(d[1]), "+f"(d[2]), "+f"(d[3])
                 : "r"(a[0]), "r"(a[1]), "r"(a[2]), "r"(a[3]), "r"(b[0]), "r"(b[1]));
}
__device__ __forceinline__ int ld_acq(const int* p) {
    int v; asm volatile("ld.acquire.gpu.global.s32 %0, [%1];" : "=r"(v) : "l"(p) : "memory");
    return v;
}
__device__ __forceinline__ void red_rel(int* p, int v) {
    asm volatile("red.release.gpu.global.add.s32 [%0], %1;" :: "l"(p), "r"(v) : "memory");
}

// ---------------- GEMM: out[m][n] = sum_k A[m][k]*W[n][k] + b1[n]+b2[n] --------
// M=32768, N=512, K in {256,512}. CTA tile 64x64, BK=32, 8 warps (2m x 4n),
// warp tile 32x16. Split-tf32 (3 MMAs) at staging.
#define GPAD 36

__global__ __launch_bounds__(256, 2) void gemm_tf32(const float* __restrict__ A,
                                                    const float* __restrict__ W,
                                                    const float* __restrict__ b1,
                                                    const float* __restrict__ b2,
                                                    float* __restrict__ out,
                                                    int K)
{
    __shared__ float Ah[64 * GPAD], Al[64 * GPAD];
    __shared__ float Bh[64 * GPAD], Bl[64 * GPAD];

    const int m0 = blockIdx.x * 64, n0 = blockIdx.y * 64;
    const int tid = threadIdx.x, lane = tid & 31, wp = tid >> 5;
    const int gid = lane >> 2, tg = lane & 3;
    const int wm = wp >> 2, wn = wp & 3;

    float acc[2][2][4];
#pragma unroll
    for (int mi = 0; mi < 2; mi++)
#pragma unroll
        for (int ni = 0; ni < 2; ni++)
#pragma unroll
            for (int c = 0; c < 4; c++) acc[mi][ni][c] = 0.f;

    for (int k0 = 0; k0 < K; k0 += 32) {
        // stage + split (A tile 64x32, B tile 64x32)
#pragma unroll
        for (int i = 0; i < 2; i++) {
            int f = tid + i * 256;          // 0..511
            int r = f >> 3, kq = (f & 7) * 4;
            float4 va = *(const float4*)(A + (size_t)(m0 + r) * K + k0 + kq);
            float4 vb = *(const float4*)(W + (size_t)(n0 + r) * K + k0 + kq);
            int o = r * GPAD + kq;
            float h;
            h = __uint_as_float(f2tf(va.x)); Ah[o + 0] = h; Al[o + 0] = va.x - h;
            h = __uint_as_float(f2tf(va.y)); Ah[o + 1] = h; Al[o + 1] = va.y - h;
            h = __uint_as_float(f2tf(va.z)); Ah[o + 2] = h; Al[o + 2] = va.z - h;
            h = __uint_as_float(f2tf(va.w)); Ah[o + 3] = h; Al[o + 3] = va.w - h;
            h = __uint_as_float(f2tf(vb.x)); Bh[o + 0] = h; Bl[o + 0] = vb.x - h;
            h = __uint_as_float(f2tf(vb.y)); Bh[o + 1] = h; Bl[o + 1] = vb.y - h;
            h = __uint_as_float(f2tf(vb.z)); Bh[o + 2] = h; Bl[o + 2] = vb.z - h;
            h = __uint_as_float(f2tf(vb.w)); Bh[o + 3] = h; Bl[o + 3] = vb.w - h;
        }
        __syncthreads();

#pragma unroll
        for (int kk = 0; kk < 4; kk++) {
            const int kb = kk * 8;
            uint32_t ahi[2][4], alo[2][4];
#pragma unroll
            for (int mi = 0; mi < 2; mi++) {
                int rb = wm * 32 + mi * 16;
                int o0 = (rb + gid) * GPAD + kb + tg;
                int o1 = (rb + gid + 8) * GPAD + kb + tg;
                ahi[mi][0] = __float_as_uint(Ah[o0]);
                ahi[mi][1] = __float_as_uint(Ah[o1]);
                ahi[mi][2] = __float_as_uint(Ah[o0 + 4]);
                ahi[mi][3] = __float_as_uint(Ah[o1 + 4]);
                alo[mi][0] = __float_as_uint(Al[o0]);
                alo[mi][1] = __float_as_uint(Al[o1]);
                alo[mi][2] = __float_as_uint(Al[o0 + 4]);
                alo[mi][3] = __float_as_uint(Al[o1 + 4]);
            }
#pragma unroll
            for (int ni = 0; ni < 2; ni++) {
                int ob = (wn * 16 + ni * 8 + gid) * GPAD + kb + tg;
                uint32_t bhi[2] = { __float_as_uint(Bh[ob]), __float_as_uint(Bh[ob + 4]) };
                uint32_t blo[2] = { __float_as_uint(Bl[ob]), __float_as_uint(Bl[ob + 4]) };
#pragma unroll
                for (int mi = 0; mi < 2; mi++) {
                    mma8(acc[mi][ni], ahi[mi], bhi);
                    mma8(acc[mi][ni], ahi[mi], blo);
                    mma8(acc[mi][ni], alo[mi], bhi);
                }
            }
        }
        __syncthreads();
    }

    // epilogue with fused bias
#pragma unroll
    for (int ni = 0; ni < 2; ni++) {
        int col = n0 + wn * 16 + ni * 8 + tg * 2;
        float z0 = b1[col] + b2[col];
        float z1 = b1[col + 1] + b2[col + 1];
#pragma unroll
        for (int mi = 0; mi < 2; mi++) {
            int r0 = m0 + wm * 32 + mi * 16 + gid;
            float2 v0 = { acc[mi][ni][0] + z0, acc[mi][ni][1] + z1 };
            float2 v1 = { acc[mi][ni][2] + z0, acc[mi][ni][3] + z1 };
            *(float2*)(out + (size_t)r0 * HH + col) = v0;
            *(float2*)(out + (size_t)(r0 + 8) * HH + col) = v1;
        }
    }
}

// ---------------- Recurrence: h_t = tanh(pre_t + h_{t-1} @ W_hh^T) -------------
// 128 CTAs = 4 batch-groups (16 batches) x 32 j-slices (16 outputs).
// W slice split (hi/lo tf32) resident in SMEM; per step: stage h (L2-only loads),
// 8 warps split K 64-wide, m16n8k8 split-tf32 accumulate, SMEM reduce, tanh,
// store, release-signal. Consumers acquire-poll flag == 32.
#define HPAD 516
#define RS_WH (16 * HPAD)
#define RSMEM_FLOATS (3 * RS_WH + 8 * 256)
#define RSMEM_BYTES  (RSMEM_FLOATS * 4)

__global__ void rnn_recur(const float* __restrict__ pre,
                          const float* __restrict__ whh,
                          float* __restrict__ hist,
                          int* __restrict__ flags)
{
    extern __shared__ float sm[];
    float* Wh = sm;                  // [16][HPAD]
    float* Wl = sm + RS_WH;
    float* Hs = sm + 2 * RS_WH;      // [16][HPAD]
    float* Rd = sm + 3 * RS_WH;      // [8 warps][16 b][16 j]

    const int tid = threadIdx.x, lane = tid & 31, wp = tid >> 5;
    const int gid = lane >> 2, tg = lane & 3;
    const int bg = blockIdx.x & 3;
    const int jg = blockIdx.x >> 2;
    const int b0 = bg * 16, jbase = jg * 16;
    const int rb = tid >> 4, rj = tid & 15;   // reduce ownership (16b x 16j)

    // Load + split this CTA's W_hh slice (16 rows x 512)
#pragma unroll
    for (int i = 0; i < 8; i++) {
        int f = tid + i * 256;       // 2048 float4s
        int j = f >> 7, k4 = (f & 127) * 4;
        float4 v = *(const float4*)(whh + (size_t)(jbase + j) * HH + k4);
        int o = j * HPAD + k4;
        float h;
        h = __uint_as_float(f2tf(v.x)); Wh[o + 0] = h; Wl[o + 0] = v.x - h;
        h = __uint_as_float(f2tf(v.y)); Wh[o + 1] = h; Wl[o + 1] = v.y - h;
        h = __uint_as_float(f2tf(v.z)); Wh[o + 2] = h; Wl[o + 2] = v.z - h;
        h = __uint_as_float(f2tf(v.w)); Wh[o + 3] = h; Wl[o + 3] = v.w - h;
    }
    __syncthreads();

    const int kw = wp * 64;          // this warp's K slice

    for (int t = 0; t < SS; t++) {
        // prefetch pre[t] early (independent of recurrence)
        float pf = __ldg(pre + ((size_t)(b0 + rb) * SS + t) * HH + jbase + rj);

        if (t > 0) {
            if (tid == 0) {
                while (ld_acq(flags + bg * SS + t - 1) < 32) { }
            }
            __syncthreads();
            // stage h_{t-1} (16 x 512) — L2-only loads (lines shared across CTAs)
#pragma unroll
            for (int i = 0; i < 8; i++) {
                int f = tid + i * 256;
                int b = f >> 7, k4 = (f & 127) * 4;
                float4 v = __ldcg((const float4*)(hist + ((size_t)(b0 + b) * SS + (t - 1)) * HH + k4));
                *(float4*)(Hs + b * HPAD + k4) = v;
            }
        } else {
#pragma unroll
            for (int i = 0; i < 8; i++) {
                int f = tid + i * 256;
                int b = f >> 7, k4 = (f & 127) * 4;
                *(float4*)(Hs + b * HPAD + k4) = make_float4(0.f, 0.f, 0.f, 0.f);
            }
        }
        __syncthreads();

        float acc[2][4];
#pragma unroll
        for (int nt = 0; nt < 2; nt++)
#pragma unroll
            for (int c = 0; c < 4; c++) acc[nt][c] = 0.f;

#pragma unroll
        for (int ks = 0; ks < 8; ks++) {
            const int kk = kw + ks * 8;
            float a0 = Hs[gid * HPAD + kk + tg];
            float a1 = Hs[(gid + 8) * HPAD + kk + tg];
            float a2 = Hs[gid * HPAD + kk + tg + 4];
            float a3 = Hs[(gid + 8) * HPAD + kk + tg + 4];
            uint32_t ahi[4] = { f2tf(a0), f2tf(a1), f2tf(a2), f2tf(a3) };
            uint32_t alo[4] = {
                __float_as_uint(a0 - __uint_as_float(ahi[0])),
                __float_as_uint(a1 - __uint_as_float(ahi[1])),
                __float_as_uint(a2 - __uint_as_float(ahi[2])),
                __float_as_uint(a3 - __uint_as_float(ahi[3]))
            };
#pragma unroll
            for (int nt = 0; nt < 2; nt++) {
                int o = (nt * 8 + gid) * HPAD + kk + tg;
                uint32_t bhi[2] = { __float_as_uint(Wh[o]), __float_as_uint(Wh[o + 4]) };
                uint32_t blo[2] = { __float_as_uint(Wl[o]), __float_as_uint(Wl[o + 4]) };
                mma8(acc[nt], ahi, bhi);
                mma8(acc[nt], ahi, blo);
                mma8(acc[nt], alo, bhi);
            }
        }

        // write partials: Rd[wp][b][j]
#pragma unroll
        for (int nt = 0; nt < 2; nt++) {
            int c0 = wp * 256 + gid * 16 + nt * 8 + tg * 2;
            Rd[c0]       = acc[nt][0];
            Rd[c0 + 1]   = acc[nt][1];
            Rd[c0 + 128] = acc[nt][2];   // (gid+8)*16
            Rd[c0 + 129] = acc[nt][3];
        }
        __syncthreads();

        // reduce 8 K-partitions, tanh, store
        {
            float s = 0.f;
#pragma unroll
            for (int r = 0; r < 8; r++) s += Rd[r * 256 + rb * 16 + rj];
            float h = tanhf(pf + s);
            hist[((size_t)(b0 + rb) * SS + t) * HH + jbase + rj] = h;
        }
        __syncthreads();
        if (tid == 0) red_rel(flags + bg * SS + t, 1);
    }
}

// ---------------- FC head ----------------
__global__ void fc_kernel(const float* __restrict__ hist1,
                          const float* __restrict__ wfc,
                          const float* __restrict__ bfc,
                          float* __restrict__ out)
{
    const int b = blockIdx.x;
    const int c = threadIdx.x >> 5;
    const int lane = threadIdx.x & 31;
    const float* h = hist1 + ((size_t)b * SS + (SS - 1)) * HH;
    float acc = 0.f;
    for (int j = lane; j < HH; j += 32) acc += h[j] * wfc[c * HH + j];
#pragma unroll
    for (int o = 16; o; o >>= 1) acc += __shfl_down_sync(0xffffffffu, acc, o);
    if (lane == 0) out[b * CC + c] = acc + bfc[c];
}

// ---------------- launch ----------------
extern "C" void kernel_launch(void* const* d_in, const int* in_sizes, int n_in,
                              void* d_out, int out_size)
{
    const float* x     = (const float*)d_in[0];
    const float* w_ih0 = (const float*)d_in[1];
    const float* w_hh0 = (const float*)d_in[2];
    const float* b_ih0 = (const float*)d_in[3];
    const float* b_hh0 = (const float*)d_in[4];
    const float* w_ih1 = (const float*)d_in[5];
    const float* w_hh1 = (const float*)d_in[6];
    const float* b_ih1 = (const float*)d_in[7];
    const float* b_hh1 = (const float*)d_in[8];
    const float* w_fc  = (const float*)d_in[9];
    const float* b_fc  = (const float*)d_in[10];
    float* out = (float*)d_out;

    float *pre0, *hist0, *pre1;
    int* flags;
    cudaGetSymbolAddress((void**)&pre0,  g_pre0);
    cudaGetSymbolAddress((void**)&hist0, g_hist0);
    cudaGetSymbolAddress((void**)&pre1,  g_pre1);
    cudaGetSymbolAddress((void**)&flags, g_flags);

    cudaFuncSetAttribute(rnn_recur,
                         cudaFuncAttributeMaxDynamicSharedMemorySize, RSMEM_BYTES);

    cudaMemsetAsync(flags, 0, 2 * 4 * SS * sizeof(int));

    dim3 gemm_grid(BB * SS / 64, HH / 64);

    // Layer 0
    gemm_tf32<<<gemm_grid, 256>>>(x, w_ih0, b_ih0, b_hh0, pre0, II);
    rnn_recur<<<128, 256, RSMEM_BYTES>>>(pre0, w_hh0, hist0, flags);

    // Layer 1 (hist1 reuses pre0 buffer)
    gemm_tf32<<<gemm_grid, 256>>>(hist0, w_ih1, b_ih1, b_hh1, pre1, HH);
    rnn_recur<<<128, 256, RSMEM_BYTES>>>(pre1, w_hh1, pre0, flags + 4 * SS);

    // Head
    fc_kernel<<<BB, CC * 32>>>(pre0, w_fc, b_fc, out);
}

// round 5
// speedup vs baseline: 1.5756x; 1.2267x over previous
#include <cuda_runtime.h>
#include <cuda_bf16.h>
#include <cstdint>

#define BB 64
#define SS 512
#define II 256
#define HH 512
#define CC 10

// ---------------- scratch ----------------
__device__ float g_pre0[(size_t)BB * SS * HH];          // GEMM0 out (fp32)
__device__ float g_pre1[(size_t)BB * SS * HH];          // GEMM1 out (fp32)
__device__ __nv_bfloat16 g_h0hi[(size_t)BB * SS * HH];  // layer0 h, split hi
__device__ __nv_bfloat16 g_h0lo[(size_t)BB * SS * HH];  // layer0 h, split lo
__device__ __nv_bfloat16 g_h1hi[(size_t)BB * SS * HH];
__device__ __nv_bfloat16 g_h1lo[(size_t)BB * SS * HH];
__device__ int g_flags[2 * 4 * SS];

// ---------------- helpers ----------------
// pack two floats to bf16x2: lower 16 = e0, upper 16 = e1
__device__ __forceinline__ uint32_t pk2(float e0, float e1) {
    uint32_t r; asm("cvt.rn.bf16x2.f32 %0, %1, %2;" : "=r"(r) : "f"(e1), "f"(e0)); return r;
}
// split float4 (4 consecutive k) into 2 hi-packed + 2 lo-packed bf16x2 regs
__device__ __forceinline__ void split4(float4 v, uint32_t& h0, uint32_t& h1,
                                       uint32_t& l0, uint32_t& l1) {
    h0 = pk2(v.x, v.y); h1 = pk2(v.z, v.w);
    float f0 = __uint_as_float(h0 << 16);
    float f1 = __uint_as_float(h0 & 0xffff0000u);
    float f2 = __uint_as_float(h1 << 16);
    float f3 = __uint_as_float(h1 & 0xffff0000u);
    l0 = pk2(v.x - f0, v.y - f1);
    l1 = pk2(v.z - f2, v.w - f3);
}
__device__ __forceinline__ void mma16(float* d, const uint32_t* a, const uint32_t* b) {
    asm volatile("mma.sync.aligned.m16n8k16.row.col.f32.bf16.bf16.f32 "
                 "{%0,%1,%2,%3},{%4,%5,%6,%7},{%8,%9},{%0,%1,%2,%3};"
                 : "+f"(d[0]), "+f"(d[1]), "+f"(d[2]), "+f"(d[3])
                 : "r"(a[0]), "r"(a[1]), "r"(a[2]), "r"(a[3]), "r"(b[0]), "r"(b[1]));
}
__device__ __forceinline__ int ld_acq(const int* p) {
    int v; asm volatile("ld.acquire.gpu.global.s32 %0, [%1];" : "=r"(v) : "l"(p) : "memory");
    return v;
}
__device__ __forceinline__ void red_rel(int* p, int v) {
    asm volatile("red.release.gpu.global.add.s32 [%0], %1;" :: "l"(p), "r"(v) : "memory");
}

// ---------------- GEMM: out[m][n] = sum_k A[m][k]*W[n][k] + b1[n]+b2[n] --------
// CTA tile 64x64, BK=32 (16 k-pairs), 8 warps (2m x 4n), warp 32x16.
// Split-bf16, 3 MMAs per k16 chunk. A either fp32 (split here) or pre-split bf16 pair.
#define GP 20   // k-pair stride (16 + 4 pad)

template<bool PACKED>
__global__ __launch_bounds__(256, 2) void gemm_bf16(const float* __restrict__ A,
                                                    const __nv_bfloat16* __restrict__ Ahg,
                                                    const __nv_bfloat16* __restrict__ Alg,
                                                    const float* __restrict__ W,
                                                    const float* __restrict__ b1,
                                                    const float* __restrict__ b2,
                                                    float* __restrict__ out,
                                                    int K)
{
    __shared__ uint32_t Ah[64 * GP], Al[64 * GP], Bh[64 * GP], Bl[64 * GP];

    const int m0 = blockIdx.x * 64, n0 = blockIdx.y * 64;
    const int tid = threadIdx.x, lane = tid & 31, wp = tid >> 5;
    const int gid = lane >> 2, tg = lane & 3;
    const int wm = wp >> 2, wn = wp & 3;

    float acc[2][2][4];
#pragma unroll
    for (int mi = 0; mi < 2; mi++)
#pragma unroll
        for (int ni = 0; ni < 2; ni++)
#pragma unroll
            for (int c = 0; c < 4; c++) acc[mi][ni][c] = 0.f;

    for (int k0 = 0; k0 < K; k0 += 32) {
        if (PACKED) {
            // A tile pre-split: straight uint4 copies (8 bf16 = 4 packed kp each)
            int r = tid >> 2, q = tid & 3;
            size_t off = (size_t)(m0 + r) * K + k0 + q * 8;
            uint4 vh = *(const uint4*)(Ahg + off);
            uint4 vl = *(const uint4*)(Alg + off);
            *(uint4*)&Ah[r * GP + q * 4] = vh;
            *(uint4*)&Al[r * GP + q * 4] = vl;
        } else {
#pragma unroll
            for (int i = 0; i < 2; i++) {
                int f = tid + i * 256;
                int r = f >> 3, kq = (f & 7);
                float4 v = *(const float4*)(A + (size_t)(m0 + r) * K + k0 + kq * 4);
                uint32_t h0, h1, l0, l1; split4(v, h0, h1, l0, l1);
                int o = r * GP + kq * 2;
                Ah[o] = h0; Ah[o + 1] = h1; Al[o] = l0; Al[o + 1] = l1;
            }
        }
#pragma unroll
        for (int i = 0; i < 2; i++) {
            int f = tid + i * 256;
            int r = f >> 3, kq = (f & 7);
            float4 v = *(const float4*)(W + (size_t)(n0 + r) * K + k0 + kq * 4);
            uint32_t h0, h1, l0, l1; split4(v, h0, h1, l0, l1);
            int o = r * GP + kq * 2;
            Bh[o] = h0; Bh[o + 1] = h1; Bl[o] = l0; Bl[o + 1] = l1;
        }
        __syncthreads();

#pragma unroll
        for (int kc = 0; kc < 2; kc++) {
            const int kb = kc * 8;
            uint32_t ahi[2][4], alo[2][4];
#pragma unroll
            for (int mi = 0; mi < 2; mi++) {
                int rb = wm * 32 + mi * 16;
                int o0 = (rb + gid) * GP + kb + tg;
                int o1 = (rb + gid + 8) * GP + kb + tg;
                ahi[mi][0] = Ah[o0]; ahi[mi][1] = Ah[o1];
                ahi[mi][2] = Ah[o0 + 4]; ahi[mi][3] = Ah[o1 + 4];
                alo[mi][0] = Al[o0]; alo[mi][1] = Al[o1];
                alo[mi][2] = Al[o0 + 4]; alo[mi][3] = Al[o1 + 4];
            }
#pragma unroll
            for (int ni = 0; ni < 2; ni++) {
                int ob = (wn * 16 + ni * 8 + gid) * GP + kb + tg;
                uint32_t bhi[2] = { Bh[ob], Bh[ob + 4] };
                uint32_t blo[2] = { Bl[ob], Bl[ob + 4] };
#pragma unroll
                for (int mi = 0; mi < 2; mi++) {
                    mma16(acc[mi][ni], ahi[mi], bhi);
                    mma16(acc[mi][ni], ahi[mi], blo);
                    mma16(acc[mi][ni], alo[mi], bhi);
                }
            }
        }
        __syncthreads();
    }

#pragma unroll
    for (int ni = 0; ni < 2; ni++) {
        int col = n0 + wn * 16 + ni * 8 + tg * 2;
        float z0 = b1[col] + b2[col];
        float z1 = b1[col + 1] + b2[col + 1];
#pragma unroll
        for (int mi = 0; mi < 2; mi++) {
            int r0 = m0 + wm * 32 + mi * 16 + gid;
            float2 v0 = { acc[mi][ni][0] + z0, acc[mi][ni][1] + z1 };
            float2 v1 = { acc[mi][ni][2] + z0, acc[mi][ni][3] + z1 };
            *(float2*)(out + (size_t)r0 * HH + col) = v0;
            *(float2*)(out + (size_t)(r0 + 8) * HH + col) = v1;
        }
    }
}

// ---------------- Recurrence: h_t = tanh(pre_t + h_{t-1} @ W_hh^T) -------------
// 128 CTAs = 4 batch-groups (16 batches) x 32 j-slices (16 outputs). W slice
// split-packed bf16x2 in SMEM once. Per step: stage pre-split h (uint4, L2),
// 8 warps x 64-k slices, 24 k16 MMAs/warp, SMEM reduce, tanh, split-store.
#define RP 260                          // k-pair stride (256 + 4)
#define RSMEM_BYTES ((4 * 16 * RP) * 4 + 8 * 256 * 4)

__global__ void rnn_recur(const float* __restrict__ pre,
                          const float* __restrict__ whh,
                          __nv_bfloat16* __restrict__ hhi,
                          __nv_bfloat16* __restrict__ hlo,
                          int* __restrict__ flags)
{
    extern __shared__ uint32_t smu[];
    uint32_t* Whp = smu;                 // [16][RP]
    uint32_t* Wlp = smu + 16 * RP;
    uint32_t* Hhp = smu + 2 * 16 * RP;   // [16][RP]
    uint32_t* Hlp = smu + 3 * 16 * RP;
    float*    Rd  = (float*)(smu + 4 * 16 * RP);  // [8][16][16]

    const int tid = threadIdx.x, lane = tid & 31, wp = tid >> 5;
    const int gid = lane >> 2, tg = lane & 3;
    const int bg = blockIdx.x & 3;
    const int jg = blockIdx.x >> 2;
    const int b0 = bg * 16, jbase = jg * 16;
    const int rb = tid >> 4, rj = tid & 15;

    // Load + split W_hh slice (16 rows x 512) into packed bf16x2 hi/lo
#pragma unroll
    for (int i = 0; i < 8; i++) {
        int f = tid + i * 256;
        int j = f >> 7, k4 = (f & 127);
        float4 v = *(const float4*)(whh + (size_t)(jbase + j) * HH + k4 * 4);
        uint32_t h0, h1, l0, l1; split4(v, h0, h1, l0, l1);
        int o = j * RP + k4 * 2;
        Whp[o] = h0; Whp[o + 1] = h1; Wlp[o] = l0; Wlp[o + 1] = l1;
    }
    __syncthreads();

    const int kpw = wp * 32;            // this warp's k-pair base (64 k)

    for (int t = 0; t < SS; t++) {
        float pf = __ldg(pre + ((size_t)(b0 + rb) * SS + t) * HH + jbase + rj);

        if (t > 0) {
            if (tid == 0) {
                while (ld_acq(flags + bg * SS + t - 1) < 32) { }
            }
            __syncthreads();
            // stage h_{t-1}: 16 batches x 512, hi + lo (already bf16x2-ready)
#pragma unroll
            for (int i = 0; i < 4; i++) {
                int f = tid + i * 256;
                int b = f >> 6, q = f & 63;
                size_t off = ((size_t)(b0 + b) * SS + (t - 1)) * HH + q * 8;
                uint4 vh = __ldcg((const uint4*)(hhi + off));
                uint4 vl = __ldcg((const uint4*)(hlo + off));
                *(uint4*)&Hhp[b * RP + q * 4] = vh;
                *(uint4*)&Hlp[b * RP + q * 4] = vl;
            }
        } else {
#pragma unroll
            for (int i = 0; i < 4; i++) {
                int f = tid + i * 256;
                int b = f >> 6, q = f & 63;
                uint4 z = make_uint4(0, 0, 0, 0);
                *(uint4*)&Hhp[b * RP + q * 4] = z;
                *(uint4*)&Hlp[b * RP + q * 4] = z;
            }
        }
        __syncthreads();

        float acc[2][4];
#pragma unroll
        for (int nt = 0; nt < 2; nt++)
#pragma unroll
            for (int c = 0; c < 4; c++) acc[nt][c] = 0.f;

#pragma unroll
        for (int kc = 0; kc < 4; kc++) {
            const int kb = kpw + kc * 8;
            int o0 = gid * RP + kb + tg;
            int o1 = (gid + 8) * RP + kb + tg;
            uint32_t ahi[4] = { Hhp[o0], Hhp[o1], Hhp[o0 + 4], Hhp[o1 + 4] };
            uint32_t alo[4] = { Hlp[o0], Hlp[o1], Hlp[o0 + 4], Hlp[o1 + 4] };
#pragma unroll
            for (int nt = 0; nt < 2; nt++) {
                int ob = (nt * 8 + gid) * RP + kb + tg;
                uint32_t bhi[2] = { Whp[ob], Whp[ob + 4] };
                uint32_t blo[2] = { Wlp[ob], Wlp[ob + 4] };
                mma16(acc[nt], ahi, bhi);
                mma16(acc[nt], ahi, blo);
                mma16(acc[nt], alo, bhi);
            }
        }

        // partials: Rd[wp][b][j]  (c0,c1 at row gid, cols 2tg/2tg+1; c2,c3 row gid+8)
#pragma unroll
        for (int nt = 0; nt < 2; nt++) {
            int c0 = wp * 256 + gid * 16 + nt * 8 + tg * 2;
            Rd[c0]       = acc[nt][0];
            Rd[c0 + 1]   = acc[nt][1];
            Rd[c0 + 128] = acc[nt][2];
            Rd[c0 + 129] = acc[nt][3];
        }
        __syncthreads();

        {
            float s = 0.f;
#pragma unroll
            for (int r = 0; r < 8; r++) s += Rd[r * 256 + rb * 16 + rj];
            float h = tanhf(pf + s);
            __nv_bfloat16 hb = __float2bfloat16(h);
            __nv_bfloat16 lb = __float2bfloat16(h - __bfloat162float(hb));
            size_t oidx = ((size_t)(b0 + rb) * SS + t) * HH + jbase + rj;
            hhi[oidx] = hb;
            hlo[oidx] = lb;
        }
        __syncthreads();
        if (tid == 0) red_rel(flags + bg * SS + t, 1);
    }
}

// ---------------- FC head ----------------
__global__ void fc_kernel(const __nv_bfloat16* __restrict__ hhi,
                          const __nv_bfloat16* __restrict__ hlo,
                          const float* __restrict__ wfc,
                          const float* __restrict__ bfc,
                          float* __restrict__ out)
{
    const int b = blockIdx.x;
    const int c = threadIdx.x >> 5;
    const int lane = threadIdx.x & 31;
    const size_t base = ((size_t)b * SS + (SS - 1)) * HH;
    float acc = 0.f;
    for (int j = lane; j < HH; j += 32) {
        float h = __bfloat162float(hhi[base + j]) + __bfloat162float(hlo[base + j]);
        acc += h * wfc[c * HH + j];
    }
#pragma unroll
    for (int o = 16; o; o >>= 1) acc += __shfl_down_sync(0xffffffffu, acc, o);
    if (lane == 0) out[b * CC + c] = acc + bfc[c];
}

// ---------------- launch ----------------
extern "C" void kernel_launch(void* const* d_in, const int* in_sizes, int n_in,
                              void* d_out, int out_size)
{
    const float* x     = (const float*)d_in[0];
    const float* w_ih0 = (const float*)d_in[1];
    const float* w_hh0 = (const float*)d_in[2];
    const float* b_ih0 = (const float*)d_in[3];
    const float* b_hh0 = (const float*)d_in[4];
    const float* w_ih1 = (const float*)d_in[5];
    const float* w_hh1 = (const float*)d_in[6];
    const float* b_ih1 = (const float*)d_in[7];
    const float* b_hh1 = (const float*)d_in[8];
    const float* w_fc  = (const float*)d_in[9];
    const float* b_fc  = (const float*)d_in[10];
    float* out = (float*)d_out;

    float *pre0, *pre1;
    __nv_bfloat16 *h0hi, *h0lo, *h1hi, *h1lo;
    int* flags;
    cudaGetSymbolAddress((void**)&pre0, g_pre0);
    cudaGetSymbolAddress((void**)&pre1, g_pre1);
    cudaGetSymbolAddress((void**)&h0hi, g_h0hi);
    cudaGetSymbolAddress((void**)&h0lo, g_h0lo);
    cudaGetSymbolAddress((void**)&h1hi, g_h1hi);
    cudaGetSymbolAddress((void**)&h1lo, g_h1lo);
    cudaGetSymbolAddress((void**)&flags, g_flags);

    cudaFuncSetAttribute(rnn_recur,
                         cudaFuncAttributeMaxDynamicSharedMemorySize, RSMEM_BYTES);

    cudaMemsetAsync(flags, 0, 2 * 4 * SS * sizeof(int));

    dim3 gemm_grid(BB * SS / 64, HH / 64);

    // Layer 0
    gemm_bf16<false><<<gemm_grid, 256>>>(x, nullptr, nullptr, w_ih0, b_ih0, b_hh0, pre0, II);
    rnn_recur<<<128, 256, RSMEM_BYTES>>>(pre0, w_hh0, h0hi, h0lo, flags);

    // Layer 1 (A operand already split)
    gemm_bf16<true><<<gemm_grid, 256>>>(nullptr, h0hi, h0lo, w_ih1, b_ih1, b_hh1, pre1, HH);
    rnn_recur<<<128, 256, RSMEM_BYTES>>>(pre1, w_hh1, h1hi, h1lo, flags + 4 * SS);

    // Head
    fc_kernel<<<BB, CC * 32>>>(h1hi, h1lo, w_fc, b_fc, out);
}